// round 1
// baseline (speedup 1.0000x reference)
#include <cuda_runtime.h>
#include <math.h>
#include <stdint.h>

#define Nn 51200
#define Ee 819200
#define Bb 64

// ---------------- scratch (__device__ globals; allocation-free) ----------------
__device__ int    d_cnt[Nn];
__device__ int    d_cur[Nn];
__device__ int    d_off[Nn + 1];
__device__ int    d_srcS[Ee];
__device__ int    d_widxS[Ee];
__device__ float4 d_basisS[Ee];
__device__ float  d_W1p[192 * 32];          // rows 0..174 = W1 flat, 175..181 = root1, rest 0
__device__ float  d_W2p[832 * 64];          // rows 0..799 = W2 flat, 800..831 = root2
__device__ float  d_U1[(size_t)Nn * 192];
__device__ float  d_h1[(size_t)Nn * 32];
__device__ float  d_U2[(size_t)Nn * 832];
__device__ float  d_h2[(size_t)Nn * 64];

__device__ __forceinline__ float eluf(float v) { return v > 0.f ? v : (expf(v) - 1.f); }

// ---------------- CSR build ----------------
__global__ void k_zero() {
    int i = blockIdx.x * blockDim.x + threadIdx.x;
    if (i < Nn) { d_cnt[i] = 0; d_cur[i] = 0; }
}

__global__ void k_hist(const int* __restrict__ dst) {
    int e = blockIdx.x * blockDim.x + threadIdx.x;
    if (e < Ee) atomicAdd(&d_cnt[dst[e]], 1);
}

__global__ void k_scan() {
    __shared__ int s[1024];
    int t = threadIdx.x;
    const int CH = (Nn + 1023) / 1024;  // 50
    int base = t * CH;
    int sum = 0;
    for (int j = 0; j < CH; j++) {
        int idx = base + j;
        if (idx < Nn) sum += d_cnt[idx];
    }
    s[t] = sum;
    __syncthreads();
    for (int ofs = 1; ofs < 1024; ofs <<= 1) {
        int v = (t >= ofs) ? s[t - ofs] : 0;
        __syncthreads();
        if (t >= ofs) s[t] += v;
        __syncthreads();
    }
    int run = (t == 0) ? 0 : s[t - 1];
    for (int j = 0; j < CH; j++) {
        int idx = base + j;
        if (idx < Nn) { d_off[idx] = run; run += d_cnt[idx]; }
    }
    if (t == 1023) d_off[Nn] = run;
}

__global__ void k_scatter(const int* __restrict__ src, const int* __restrict__ dst,
                          const float* __restrict__ pseudo) {
    int e = blockIdx.x * blockDim.x + threadIdx.x;
    if (e >= Ee) return;
    int d = dst[e];
    int pos = d_off[d] + atomicAdd(&d_cur[d], 1);
    d_srcS[pos] = src[e];
    float v0 = pseudo[2 * e] * 4.f;
    float v1 = pseudo[2 * e + 1] * 4.f;
    int lo0 = __float2int_rd(v0); lo0 = lo0 < 0 ? 0 : (lo0 > 3 ? 3 : lo0);
    int lo1 = __float2int_rd(v1); lo1 = lo1 < 0 ? 0 : (lo1 > 3 ? 3 : lo1);
    float f0 = v0 - (float)lo0, f1 = v1 - (float)lo1;
    float g0 = 1.f - f0, g1 = 1.f - f1;
    d_basisS[pos] = make_float4(g0 * g1, g0 * f1, f0 * g1, f0 * f1);
    int k0 = lo0 * 5 + lo1;
    d_widxS[pos] = k0 | ((k0 + 1) << 8) | ((k0 + 5) << 16) | ((k0 + 6) << 24);
}

// ---------------- weight prep (fold root into GEMM weights) ----------------
__global__ void k_wprep(const float* __restrict__ W1, const float* __restrict__ root1,
                        const float* __restrict__ W2, const float* __restrict__ root2) {
    int j = blockIdx.x * blockDim.x + threadIdx.x;
    if (j < 192 * 32) {
        float v = 0.f;
        if (j < 5600) v = W1[j];
        else if (j < 5824) v = root1[j - 5600];
        d_W1p[j] = v;
    }
    if (j < 832 * 64) {
        float v;
        if (j < 51200) v = W2[j];
        else v = root2[j - 51200];
        d_W2p[j] = v;
    }
}

// ---------------- U1 build: per node accumulate u[k*7+i], 4 edges in flight ----------------
__global__ void k_u1(const float* __restrict__ x) {
    __shared__ float su[8][4][176];
    int tid = threadIdx.x;
    int warp = tid >> 5, lane = tid & 31;
    int n = blockIdx.x * 8 + warp;
    if (n >= Nn) return;
    float(*u)[176] = su[warp];
    for (int j = lane; j < 4 * 176; j += 32) ((float*)u)[j] = 0.f;
    __syncwarp();
    int beg = d_off[n], end = d_off[n + 1];
    int eb = lane / 7, i = lane - eb * 7;
    if (lane < 28) {
        for (int p0 = beg; p0 < end; p0 += 4) {
            int p = p0 + eb;
            if (p < end) {
                int sv = d_srcS[p];
                float4 bs = d_basisS[p];
                int wx = d_widxS[p];
                float xv = x[sv * 7 + i];
                u[eb][(wx & 255) * 7 + i]         += bs.x * xv;
                u[eb][((wx >> 8) & 255) * 7 + i]  += bs.y * xv;
                u[eb][((wx >> 16) & 255) * 7 + i] += bs.z * xv;
                u[eb][((wx >> 24) & 255) * 7 + i] += bs.w * xv;
            }
        }
    }
    __syncwarp();
    float inv = 1.f / fmaxf((float)(end - beg), 1.f);
    for (int j = lane; j < 192; j += 32) {
        float v;
        if (j < 175)      v = (u[0][j] + u[1][j] + u[2][j] + u[3][j]) * inv;
        else if (j < 182) v = x[n * 7 + (j - 175)];
        else              v = 0.f;
        d_U1[(size_t)n * 192 + j] = v;
    }
}

// ---------------- U2 build: lane = channel, lane-exclusive smem slots ----------------
__global__ void k_u2() {
    __shared__ float su[8][800];
    int tid = threadIdx.x;
    int warp = tid >> 5, lane = tid & 31;
    int n = blockIdx.x * 8 + warp;
    if (n >= Nn) return;
    float* u = su[warp];
    for (int j = lane; j < 800; j += 32) u[j] = 0.f;
    __syncwarp();
    int beg = d_off[n], end = d_off[n + 1];
    for (int p = beg; p < end; p++) {
        int sv = d_srcS[p];
        float4 bs = d_basisS[p];
        int wx = d_widxS[p];
        float hv = d_h1[(size_t)sv * 32 + lane];
        u[(wx & 255) * 32 + lane]         += bs.x * hv;
        u[((wx >> 8) & 255) * 32 + lane]  += bs.y * hv;
        u[((wx >> 16) & 255) * 32 + lane] += bs.z * hv;
        u[((wx >> 24) & 255) * 32 + lane] += bs.w * hv;
    }
    __syncwarp();
    float inv = 1.f / fmaxf((float)(end - beg), 1.f);
    for (int j = lane; j < 832; j += 32) {
        float v = (j < 800) ? u[j] * inv : d_h1[(size_t)n * 32 + (j - 800)];
        d_U2[(size_t)n * 832 + j] = v;
    }
}

// component picker (kk&7 is a compile-time constant under unroll)
#define COMP(F0, F1, c) ((c) == 0 ? (F0).x : (c) == 1 ? (F0).y : (c) == 2 ? (F0).z : (c) == 3 ? (F0).w : \
                         (c) == 4 ? (F1).x : (c) == 5 ? (F1).y : (c) == 6 ? (F1).z : (F1).w)

// ---------------- GEMM1: h1 = elu(U1(N,192) @ W1p(192,32) + b1) ----------------
__global__ void __launch_bounds__(512) k_gemm1(const float* __restrict__ b1) {
    __shared__ float Ws[192 * 32];
    const int tid = threadIdx.x, lane = tid & 31, warp = tid >> 5;
    for (int j = tid; j < 192 * 32 / 4; j += 512)
        ((float4*)Ws)[j] = ((const float4*)d_W1p)[j];
    __syncthreads();
    const int m0 = blockIdx.x * 128 + warp * 8;
    float acc[8];
#pragma unroll
    for (int r = 0; r < 8; r++) acc[r] = 0.f;
    const int rl = lane >> 2, kl = (lane & 3) * 8;
    const float* aBase = &d_U1[(size_t)(m0 + rl) * 192 + kl];
    float4 f0 = *(const float4*)(aBase);
    float4 f1 = *(const float4*)(aBase + 4);
    for (int kb = 0; kb < 192; kb += 32) {
        float4 n0, n1;
        if (kb + 32 < 192) {
            n0 = *(const float4*)(aBase + kb + 32);
            n1 = *(const float4*)(aBase + kb + 36);
        }
#pragma unroll
        for (int kk = 0; kk < 32; kk++) {
            float w = Ws[(kb + kk) * 32 + lane];
            float srcv = COMP(f0, f1, kk & 7);
#pragma unroll
            for (int r = 0; r < 8; r++) {
                float a = __shfl_sync(0xffffffffu, srcv, (r << 2) | (kk >> 3), 32);
                acc[r] += a * w;
            }
        }
        f0 = n0; f1 = n1;
    }
    float bv = b1[lane];
#pragma unroll
    for (int r = 0; r < 8; r++)
        d_h1[(size_t)(m0 + r) * 32 + lane] = eluf(acc[r] + bv);
}

// ---------------- GEMM2: h2 = elu(U2(N,832) @ W2p(832,64) + b2) ----------------
__global__ void __launch_bounds__(512) k_gemm2(const float* __restrict__ b2) {
    extern __shared__ float Ws[];  // 832*64 floats = 212992 B
    const int tid = threadIdx.x, lane = tid & 31, warp = tid >> 5;
    for (int j = tid; j < 832 * 64 / 4; j += 512)
        ((float4*)Ws)[j] = ((const float4*)d_W2p)[j];
    __syncthreads();
    const int m0 = blockIdx.x * 128 + warp * 8;
    const int o0 = lane * 2;
    float acc[8][2];
#pragma unroll
    for (int r = 0; r < 8; r++) { acc[r][0] = 0.f; acc[r][1] = 0.f; }
    const int rl = lane >> 2, kl = (lane & 3) * 8;
    const float* aBase = &d_U2[(size_t)(m0 + rl) * 832 + kl];
    float4 f0 = *(const float4*)(aBase);
    float4 f1 = *(const float4*)(aBase + 4);
    for (int kb = 0; kb < 832; kb += 32) {
        float4 n0, n1;
        if (kb + 32 < 832) {
            n0 = *(const float4*)(aBase + kb + 32);
            n1 = *(const float4*)(aBase + kb + 36);
        }
        const float* wp = &Ws[kb * 64 + o0];
#pragma unroll
        for (int kk = 0; kk < 32; kk++) {
            float2 w = *(const float2*)(wp + kk * 64);
            float srcv = COMP(f0, f1, kk & 7);
#pragma unroll
            for (int r = 0; r < 8; r++) {
                float a = __shfl_sync(0xffffffffu, srcv, (r << 2) | (kk >> 3), 32);
                acc[r][0] += a * w.x;
                acc[r][1] += a * w.y;
            }
        }
        f0 = n0; f1 = n1;
    }
    float bv0 = b2[o0], bv1 = b2[o0 + 1];
#pragma unroll
    for (int r = 0; r < 8; r++) {
        float v0 = eluf(acc[r][0] + bv0);
        float v1 = eluf(acc[r][1] + bv1);
        *(float2*)&d_h2[(size_t)(m0 + r) * 64 + o0] = make_float2(v0, v1);
    }
}

// ---------------- pooling + FC + log_softmax ----------------
__global__ void k_head(const int* __restrict__ slices, const float* __restrict__ fcw,
                       const float* __restrict__ fcb, float* __restrict__ out) {
    int b = blockIdx.x;
    int s0 = slices[b], s1 = slices[b + 1];
    __shared__ float red[4][64];
    __shared__ float g[64];
    __shared__ float lg[30];
    int tid = threadIdx.x;  // 256
    int o = tid & 63, part = tid >> 6;
    float acc = 0.f;
    for (int n = s0 + part; n < s1; n += 4) acc += d_h2[(size_t)n * 64 + o];
    red[part][o] = acc;
    __syncthreads();
    if (part == 0) {
        float s = red[0][o] + red[1][o] + red[2][o] + red[3][o];
        g[o] = s / fmaxf((float)(s1 - s0), 1.f);
    }
    __syncthreads();
    if (tid < 30) {
        float l = fcb[tid];
        for (int i = 0; i < 64; i++) l += g[i] * fcw[i * 30 + tid];
        lg[tid] = l;
    }
    __syncthreads();
    if (tid < 30) {
        float m = -1e30f;
        for (int j = 0; j < 30; j++) m = fmaxf(m, lg[j]);
        float se = 0.f;
        for (int j = 0; j < 30; j++) se += expf(lg[j] - m);
        out[b * 30 + tid] = lg[tid] - m - logf(se);
    }
}

// ---------------- launch ----------------
extern "C" void kernel_launch(void* const* d_in, const int* in_sizes, int n_in,
                              void* d_out, int out_size) {
    const float* x      = (const float*)d_in[0];
    const int*   eidx   = (const int*)d_in[1];
    const float* pseudo = (const float*)d_in[2];
    const int*   slices = (const int*)d_in[3];
    const float* W1     = (const float*)d_in[4];
    const float* root1  = (const float*)d_in[5];
    const float* b1     = (const float*)d_in[6];
    const float* W2     = (const float*)d_in[7];
    const float* root2  = (const float*)d_in[8];
    const float* b2     = (const float*)d_in[9];
    const float* fcw    = (const float*)d_in[10];
    const float* fcb    = (const float*)d_in[11];
    float* out = (float*)d_out;

    const int* src = eidx;
    const int* dst = eidx + Ee;

    cudaFuncSetAttribute(k_gemm2, cudaFuncAttributeMaxDynamicSharedMemorySize, 832 * 64 * 4);

    k_zero<<<(Nn + 255) / 256, 256>>>();
    k_hist<<<(Ee + 1023) / 1024, 1024>>>(dst);
    k_scan<<<1, 1024>>>();
    k_scatter<<<(Ee + 1023) / 1024, 1024>>>(src, dst, pseudo);
    k_wprep<<<(832 * 64 + 255) / 256, 256>>>(W1, root1, W2, root2);
    k_u1<<<Nn / 8, 256>>>(x);
    k_gemm1<<<Nn / 128, 512>>>(b1);
    k_u2<<<Nn / 8, 256>>>();
    k_gemm2<<<Nn / 128, 512, 832 * 64 * 4>>>(b2);
    k_head<<<Bb, 256>>>(slices, fcw, fcb, out);
}